// round 7
// baseline (speedup 1.0000x reference)
#include <cuda_runtime.h>

#define BB 16
#define NN 2048
#define CC 256
#define RR 128
#define KK 16

// ---------------- static device scratch ----------------
__device__ float g_xpre[BB * RR * NN];   // mlp1 pre-BN, channel-major
__device__ int   g_idx[BB * NN * KK];    // top-16 neighbor indices
__device__ float g_y[BB * NN * RR];      // fc(relu(bn1(xpre))), point-major
__device__ float g_x2c[BB * RR * NN];    // group-max output, channel-major
__device__ float g_lapc[BB * RR * NN];   // laplacian, channel-major
__device__ float g_t[BB * RR * NN];      // lu output pre-BN, channel-major
__device__ float g_y2[BB * CC * NN];     // mlp2 pre-BN, channel-major
__device__ float g_y3[BB * 2 * CC * NN]; // mlp3 pre-BN, channel-major
__device__ int   g_cnt[BB * NN];         // gather histogram for BNg
__device__ float g_stat[2304];           // per-BN sums / sumsqs
__device__ float g_aff[2304];            // per-BN scale / shift

__device__ __forceinline__ float tf32r(float x) {
    float o;
    asm("cvt.rna.tf32.f32 %0, %1;" : "=f"(o) : "f"(x));
    return o;
}

// ---------------- zero accumulators ----------------
__global__ void k_zero() {
    int i = blockIdx.x * 256 + threadIdx.x;
    if (i < BB * NN) g_cnt[i] = 0;
    if (i < 2304)    g_stat[i] = 0.f;
}

// ---------------- kNN top-16 on 2D coords (exact fp32, XLA association) ----------------
__global__ void k_knn(const float* __restrict__ xyz) {
    __shared__ float sx[NN];
    __shared__ float sy[NN];
    __shared__ float sxx[NN];  // add(mul(x,x), mul(y,y)) — matches jnp.sum(x*x)
    int b = blockIdx.y;
    const float* px = xyz + (size_t)b * 3 * NN;
    for (int i = threadIdx.x; i < NN; i += 256) {
        float xv = px[i], yv = px[NN + i];
        sx[i] = xv; sy[i] = yv;
        sxx[i] = __fadd_rn(__fmul_rn(xv, xv), __fmul_rn(yv, yv));
    }
    __syncthreads();
    int n = blockIdx.x * 256 + threadIdx.x;
    float qx = sx[n], qy = sy[n], qxx = sxx[n];
    float bd[KK];
    int   bi[KK];
#pragma unroll
    for (int j = 0; j < KK; j++) { bd[j] = 3.4e38f; bi[j] = 0; }
    for (int m = 0; m < NN; m++) {
        // dot over c ascending: fma(y, y', round(x*x')) — matches XLA contraction
        float inner = __fmaf_rn(qy, sy[m], __fmul_rn(qx, sx[m]));
        // dist = (xx_n - 2*inner) + xx_m, matching XLA association
        float d = __fadd_rn(__fsub_rn(qxx, 2.f * inner), sxx[m]);
        if (d < bd[KK - 1]) {
            bd[KK - 1] = d; bi[KK - 1] = m;
#pragma unroll
            for (int j = KK - 1; j >= 1; j--) {
                if (bd[j] < bd[j - 1]) {
                    float td = bd[j]; bd[j] = bd[j - 1]; bd[j - 1] = td;
                    int   ti = bi[j]; bi[j] = bi[j - 1]; bi[j - 1] = ti;
                }
            }
        }
    }
    int* op = g_idx + ((size_t)b * NN + n) * KK;
#pragma unroll
    for (int j = 0; j < KK; j++) op[j] = bi[j];
}

// ---------------- histogram of first-8 neighbor indices ----------------
__global__ void k_cnt() {
    int b = blockIdx.x;
    for (int row = threadIdx.x; row < NN; row += blockDim.x) {
        const int* p = g_idx + ((size_t)b * NN + row) * KK;
#pragma unroll
        for (int j = 0; j < 8; j++) atomicAdd(&g_cnt[b * NN + p[j]], 1);
    }
}

// ---------------- tiled GEMM (TF32-emulated inputs): out = W @ f(in) + bias ----------------
// MODE 0: raw input. MODE 1: relu(in*scale[k]+shift[k]). MODE 2: MODE1 + add.
// OUT_PM 0: out[b][m][n] (channel-major). OUT_PM 1: out[b][n][m] (point-major).
template <int MODE, int OUT_PM>
__global__ void k_gemm(const float* __restrict__ W, const float* __restrict__ in,
                       const float* __restrict__ bias,
                       const float* __restrict__ scale, const float* __restrict__ shift,
                       const float* __restrict__ add,
                       float* __restrict__ out, int M, int Kd) {
    __shared__ __align__(16) float Ws[16][68];
    __shared__ __align__(16) float Xs[16][68];
    int b = blockIdx.z;
    int n0 = blockIdx.x * 64, m0 = blockIdx.y * 64;
    int tid = threadIdx.x;
    int tx = tid & 15, ty = tid >> 4;
    const float* inb = in + (size_t)b * Kd * NN;
    const float* addb = (MODE == 2) ? add + (size_t)b * Kd * NN : in;
    float acc[4][4];
#pragma unroll
    for (int i = 0; i < 4; i++)
#pragma unroll
        for (int j = 0; j < 4; j++) acc[i][j] = 0.f;

    for (int k0 = 0; k0 < Kd; k0 += 16) {
        int kw = tid & 15, mw = tid >> 4;
#pragma unroll
        for (int p = 0; p < 4; p++)
            Ws[kw][mw + p * 16] = tf32r(W[(size_t)(m0 + mw + p * 16) * Kd + k0 + kw]);
        int nn2 = tid & 63, kk = tid >> 6;
#pragma unroll
        for (int p = 0; p < 4; p++) {
            int kg = k0 + kk + p * 4;
            float v = inb[(size_t)kg * NN + n0 + nn2];
            if (MODE >= 1) v = fmaxf(fmaf(v, scale[kg], shift[kg]), 0.f);
            if (MODE == 2) v += addb[(size_t)kg * NN + n0 + nn2];
            Xs[kk + p * 4][nn2] = tf32r(v);
        }
        __syncthreads();
#pragma unroll
        for (int kk2 = 0; kk2 < 16; kk2++) {
            float4 xv = *reinterpret_cast<const float4*>(&Xs[kk2][tx * 4]);
            float4 wv = *reinterpret_cast<const float4*>(&Ws[kk2][ty * 4]);
            float xa[4] = {xv.x, xv.y, xv.z, xv.w};
            float wa[4] = {wv.x, wv.y, wv.z, wv.w};
#pragma unroll
            for (int i = 0; i < 4; i++)
#pragma unroll
                for (int j = 0; j < 4; j++)
                    acc[i][j] = fmaf(wa[i], xa[j], acc[i][j]);
        }
        __syncthreads();
    }
    if (OUT_PM == 0) {
#pragma unroll
        for (int i = 0; i < 4; i++) {
            int m = m0 + ty * 4 + i;
            float bv = bias[m];
            float4 o = make_float4(acc[i][0] + bv, acc[i][1] + bv,
                                   acc[i][2] + bv, acc[i][3] + bv);
            *reinterpret_cast<float4*>(&out[((size_t)b * M + m) * NN + n0 + tx * 4]) = o;
        }
    } else {
#pragma unroll
        for (int j = 0; j < 4; j++) {
            int n = n0 + tx * 4 + j;
            int m = m0 + ty * 4;
            float4 o = make_float4(acc[0][j] + bias[m],     acc[1][j] + bias[m + 1],
                                   acc[2][j] + bias[m + 2], acc[3][j] + bias[m + 3]);
            *reinterpret_cast<float4*>(&out[((size_t)b * NN + n) * M + m]) = o;
        }
    }
}

// ---------------- per-channel stats over channel-major [B,M,N] ----------------
__global__ void k_stats(const float* __restrict__ src, int M, int offS, int offQ) {
    int m = blockIdx.x, b = blockIdx.y;
    const float* p = src + ((size_t)b * M + m) * NN;
    float s = 0.f, q = 0.f;
    for (int i = threadIdx.x; i < NN; i += 256) { float v = p[i]; s += v; q += v * v; }
    __shared__ float ss[256], sq[256];
    ss[threadIdx.x] = s; sq[threadIdx.x] = q; __syncthreads();
    for (int st = 128; st > 0; st >>= 1) {
        if (threadIdx.x < st) { ss[threadIdx.x] += ss[threadIdx.x + st]; sq[threadIdx.x] += sq[threadIdx.x + st]; }
        __syncthreads();
    }
    if (threadIdx.x == 0) { atomicAdd(&g_stat[offS + m], ss[0]); atomicAdd(&g_stat[offQ + m], sq[0]); }
}

// ---------------- weighted stats for BNg (counts * fc output) ----------------
__global__ void k_statw() {
    int b = blockIdx.y, mc = blockIdx.x;
    int r = threadIdx.x;
    float s = 0.f, q = 0.f;
    for (int m = mc * 128; m < mc * 128 + 128; m++) {
        float c = (float)g_cnt[b * NN + m];
        float v = g_y[((size_t)b * NN + m) * RR + r];
        s += c * v; q += c * v * v;
    }
    atomicAdd(&g_stat[256 + r], s);
    atomicAdd(&g_stat[384 + r], q);
}

// ---------------- finalize BN affine ----------------
__global__ void k_fin(const float* __restrict__ gamma, const float* __restrict__ beta,
                      int M, int offS, int offQ, float invcnt) {
    int m = blockIdx.x * 256 + threadIdx.x;
    if (m >= M) return;
    float mu = g_stat[offS + m] * invcnt;
    float var = g_stat[offQ + m] * invcnt - mu * mu;
    float sc = gamma[m] * rsqrtf(var + 1e-5f);
    g_aff[offS + m] = sc;
    g_aff[offQ + m] = beta[m] - mu * sc;
}

// ---------------- group max: x2[b][r][n2] = max_kg relu(bng(y[.,J])) ----------------
__global__ void k_gmax() {
    int n2 = blockIdx.x, b = blockIdx.y;
    __shared__ int sj[8];
    int r = threadIdx.x;
    if (r < 8)
        sj[r] = g_idx[((size_t)b * NN + r * 256 + (n2 >> 3)) * KK + (n2 & 7)];
    __syncthreads();
    float sc = g_aff[256 + r], sh = g_aff[384 + r];
    float u = 0.f;
#pragma unroll
    for (int kg = 0; kg < 8; kg++) {
        float v = g_y[((size_t)b * NN + sj[kg]) * RR + r];
        u = fmaxf(u, fmaxf(fmaf(v, sc, sh), 0.f));
    }
    g_x2c[((size_t)b * RR + r) * NN + n2] = u;
}

// ---------------- laplacian with faithful .view index algebra ----------------
__global__ void k_lap() {
    int n2 = blockIdx.x, b = blockIdx.y;
    int p = n2 >> 4, s = n2 & 15;
    __shared__ float xr[NN];
    __shared__ int si[2048];
    const float* src = g_x2c + ((size_t)b * RR + p) * NN;
    const int* ib = g_idx + ((size_t)b * NN + s * 128) * KK;
    for (int i = threadIdx.x; i < NN; i += 128) { xr[i] = src[i]; si[i] = ib[i]; }
    __syncthreads();
    int r2 = threadIdx.x;
    int u = r2 >> 4, j = r2 & 15;
    float acc = 0.f;
#pragma unroll
    for (int k2 = 0; k2 < 16; k2++)
        acc += xr[si[(k2 * 8 + u) * 16 + j]];
    float own = g_x2c[((size_t)b * RR + r2) * NN + n2];
    g_lapc[((size_t)b * RR + r2) * NN + n2] = own - acc * (1.f / 16.f);
}

// ---------------- final BN3 apply ----------------
__global__ void k_apply(float* __restrict__ out) {
    int i = blockIdx.x * 256 + threadIdx.x;
    int c = (i >> 11) & 511;
    float v = g_y3[i];
    out[i] = fmaxf(fmaf(v, g_aff[1280 + c], g_aff[1792 + c]), 0.f);
}

extern "C" void kernel_launch(void* const* d_in, const int* in_sizes, int n_in,
                              void* d_out, int out_size) {
    const float* xyz   = (const float*)d_in[0];
    const float* feat  = (const float*)d_in[1];
    const float* w1    = (const float*)d_in[2];
    const float* b1    = (const float*)d_in[3];
    const float* bn1_g = (const float*)d_in[4];
    const float* bn1_b = (const float*)d_in[5];
    const float* fc_w  = (const float*)d_in[6];
    const float* fc_b  = (const float*)d_in[7];
    const float* bng_g = (const float*)d_in[8];
    const float* bng_b = (const float*)d_in[9];
    const float* lu_w  = (const float*)d_in[10];
    const float* lu_b  = (const float*)d_in[11];
    const float* bnl_g = (const float*)d_in[12];
    const float* bnl_b = (const float*)d_in[13];
    const float* w2    = (const float*)d_in[14];
    const float* b2    = (const float*)d_in[15];
    const float* bn2_g = (const float*)d_in[16];
    const float* bn2_b = (const float*)d_in[17];
    const float* w3    = (const float*)d_in[18];
    const float* b3    = (const float*)d_in[19];
    const float* bn3_g = (const float*)d_in[20];
    const float* bn3_b = (const float*)d_in[21];
    float* out = (float*)d_out;

    float *xpre, *y, *x2c, *lapc, *t, *y2, *y3, *aff;
    cudaGetSymbolAddress((void**)&xpre, g_xpre);
    cudaGetSymbolAddress((void**)&y,    g_y);
    cudaGetSymbolAddress((void**)&x2c,  g_x2c);
    cudaGetSymbolAddress((void**)&lapc, g_lapc);
    cudaGetSymbolAddress((void**)&t,    g_t);
    cudaGetSymbolAddress((void**)&y2,   g_y2);
    cudaGetSymbolAddress((void**)&y3,   g_y3);
    cudaGetSymbolAddress((void**)&aff,  g_aff);

    k_zero<<<128, 256>>>();
    k_knn<<<dim3(8, BB), 256>>>(xyz);
    k_cnt<<<BB, 512>>>();

    // mlp1: xpre = w1 @ feat + b1
    k_gemm<0, 0><<<dim3(32, 2, BB), 256>>>(w1, feat, b1, nullptr, nullptr, nullptr, xpre, RR, CC);
    k_stats<<<dim3(RR, BB), 256>>>(xpre, RR, 0, 128);
    k_fin<<<1, 256>>>(bn1_g, bn1_b, RR, 0, 128, 1.f / (BB * NN));

    // fc applied pre-gather: y[b][n][r] = fc_w @ relu(bn1(xpre)) + fc_b (point-major)
    k_gemm<1, 1><<<dim3(32, 2, BB), 256>>>(fc_w, xpre, fc_b, aff, aff + 128, nullptr, y, RR, RR);
    k_statw<<<dim3(16, BB), 128>>>();
    k_fin<<<1, 256>>>(bng_g, bng_b, RR, 256, 384, 1.f / 262144.f);

    k_gmax<<<dim3(NN, BB), 128>>>();
    k_lap<<<dim3(NN, BB), 128>>>();

    // lu: t = lu_w @ lap + lu_b
    k_gemm<0, 0><<<dim3(32, 2, BB), 256>>>(lu_w, lapc, lu_b, nullptr, nullptr, nullptr, t, RR, RR);
    k_stats<<<dim3(RR, BB), 256>>>(t, RR, 512, 640);
    k_fin<<<1, 256>>>(bnl_g, bnl_b, RR, 512, 640, 1.f / (BB * NN));

    // mlp2: y2 = w2 @ (x2 + relu(bnl(t))) + b2
    k_gemm<2, 0><<<dim3(32, 4, BB), 256>>>(w2, t, b2, aff + 512, aff + 640, x2c, y2, CC, RR);
    k_stats<<<dim3(CC, BB), 256>>>(y2, CC, 768, 1024);
    k_fin<<<1, 256>>>(bn2_g, bn2_b, CC, 768, 1024, 1.f / (BB * NN));

    // mlp3: y3 = w3 @ (relu(bn2(y2)) + feat) + b3
    k_gemm<2, 0><<<dim3(32, 8, BB), 256>>>(w3, y2, b3, aff + 768, aff + 1024, feat, y3, 2 * CC, CC);
    k_stats<<<dim3(2 * CC, BB), 256>>>(y3, 2 * CC, 1280, 1792);
    k_fin<<<2, 256>>>(bn3_g, bn3_b, 2 * CC, 1280, 1792, 1.f / (BB * NN));

    k_apply<<<65536, 256>>>(out);
}

// round 9
// speedup vs baseline: 1.0826x; 1.0826x over previous
#include <cuda_runtime.h>

#define BB 16
#define NN 2048
#define CC 256
#define RR 128
#define KK 16

// ---------------- static device scratch ----------------
__device__ float g_xpre[BB * RR * NN];   // mlp1 pre-BN, channel-major
__device__ int   g_idx[BB * NN * KK];    // top-16 neighbor indices
__device__ float g_y[BB * NN * RR];      // fc(relu(bn1(xpre))), point-major
__device__ float g_x2c[BB * RR * NN];    // group-max output, channel-major
__device__ float g_lapc[BB * RR * NN];   // laplacian, channel-major
__device__ float g_t[BB * RR * NN];      // lu output pre-BN, channel-major
__device__ float g_y2[BB * CC * NN];     // mlp2 pre-BN, channel-major
__device__ float g_y3[BB * 2 * CC * NN]; // mlp3 pre-BN, channel-major
__device__ int   g_cnt[BB * NN];         // gather histogram for BNg
__device__ float g_stat[2304];           // per-BN sums / sumsqs
__device__ float g_aff[2304];            // per-BN scale / shift

__device__ __forceinline__ float tf32r(float x) {
    float o;
    asm("cvt.rna.tf32.f32 %0, %1;" : "=f"(o) : "f"(x));
    return o;
}

// ---------------- zero accumulators ----------------
__global__ void k_zero() {
    int i = blockIdx.x * 256 + threadIdx.x;
    if (i < BB * NN) g_cnt[i] = 0;
    if (i < 2304)    g_stat[i] = 0.f;
}

// ---------------- kNN top-16 on 2D coords (exact fp32, XLA association) ----------------
__global__ void k_knn(const float* __restrict__ xyz) {
    __shared__ float sx[NN];
    __shared__ float sy[NN];
    __shared__ float sxx[NN];  // add(mul(x,x), mul(y,y)) — matches jnp.sum(x*x)
    int b = blockIdx.y;
    const float* px = xyz + (size_t)b * 3 * NN;
    for (int i = threadIdx.x; i < NN; i += 256) {
        float xv = px[i], yv = px[NN + i];
        sx[i] = xv; sy[i] = yv;
        sxx[i] = __fadd_rn(__fmul_rn(xv, xv), __fmul_rn(yv, yv));
    }
    __syncthreads();
    int n = blockIdx.x * 256 + threadIdx.x;
    float qx = sx[n], qy = sy[n], qxx = sxx[n];
    float bd[KK];
    int   bi[KK];
#pragma unroll
    for (int j = 0; j < KK; j++) { bd[j] = 3.4e38f; bi[j] = 0; }
    for (int m = 0; m < NN; m++) {
        float inner = __fmaf_rn(qy, sy[m], __fmul_rn(qx, sx[m]));
        float d = __fadd_rn(__fsub_rn(qxx, 2.f * inner), sxx[m]);
        if (d < bd[KK - 1]) {
            bd[KK - 1] = d; bi[KK - 1] = m;
#pragma unroll
            for (int j = KK - 1; j >= 1; j--) {
                if (bd[j] < bd[j - 1]) {
                    float td = bd[j]; bd[j] = bd[j - 1]; bd[j - 1] = td;
                    int   ti = bi[j]; bi[j] = bi[j - 1]; bi[j - 1] = ti;
                }
            }
        }
    }
    int* op = g_idx + ((size_t)b * NN + n) * KK;
#pragma unroll
    for (int j = 0; j < KK; j++) op[j] = bi[j];
}

// ---------------- histogram of first-8 neighbor indices ----------------
__global__ void k_cnt() {
    int b = blockIdx.x;
    for (int row = threadIdx.x; row < NN; row += blockDim.x) {
        const int* p = g_idx + ((size_t)b * NN + row) * KK;
#pragma unroll
        for (int j = 0; j < 8; j++) atomicAdd(&g_cnt[b * NN + p[j]], 1);
    }
}

// ---------------- tiled GEMM (TF32-emulated inputs): out = W @ f(in) + bias ----------------
// MODE 0: raw input. MODE 1: relu(in*scale[k]+shift[k]). MODE 2: MODE1 + add.
// OUT_PM 0: out[b][m][n] (channel-major). OUT_PM 1: out[b][n][m] (point-major).
// offS >= 0: fused BN stats (sum at g_stat[offS+m], sumsq at g_stat[offS+M+m]).
template <int MODE, int OUT_PM>
__global__ void k_gemm(const float* __restrict__ W, const float* __restrict__ in,
                       const float* __restrict__ bias,
                       const float* __restrict__ scale, const float* __restrict__ shift,
                       const float* __restrict__ add,
                       float* __restrict__ out, int M, int Kd, int offS) {
    __shared__ __align__(16) float Ws[16][68];
    __shared__ __align__(16) float Xs[16][68];
    int b = blockIdx.z;
    int n0 = blockIdx.x * 64, m0 = blockIdx.y * 64;
    int tid = threadIdx.x;
    int tx = tid & 15, ty = tid >> 4;
    const float* inb = in + (size_t)b * Kd * NN;
    const float* addb = (MODE == 2) ? add + (size_t)b * Kd * NN : in;
    float acc[4][4];
#pragma unroll
    for (int i = 0; i < 4; i++)
#pragma unroll
        for (int j = 0; j < 4; j++) acc[i][j] = 0.f;

    for (int k0 = 0; k0 < Kd; k0 += 16) {
        int kw = tid & 15, mw = tid >> 4;
#pragma unroll
        for (int p = 0; p < 4; p++)
            Ws[kw][mw + p * 16] = tf32r(W[(size_t)(m0 + mw + p * 16) * Kd + k0 + kw]);
        int nn2 = tid & 63, kk = tid >> 6;
#pragma unroll
        for (int p = 0; p < 4; p++) {
            int kg = k0 + kk + p * 4;
            float v = inb[(size_t)kg * NN + n0 + nn2];
            if (MODE >= 1) v = fmaxf(fmaf(v, scale[kg], shift[kg]), 0.f);
            if (MODE == 2) v += addb[(size_t)kg * NN + n0 + nn2];
            Xs[kk + p * 4][nn2] = tf32r(v);
        }
        __syncthreads();
#pragma unroll
        for (int kk2 = 0; kk2 < 16; kk2++) {
            float4 xv = *reinterpret_cast<const float4*>(&Xs[kk2][tx * 4]);
            float4 wv = *reinterpret_cast<const float4*>(&Ws[kk2][ty * 4]);
            float xa[4] = {xv.x, xv.y, xv.z, xv.w};
            float wa[4] = {wv.x, wv.y, wv.z, wv.w};
#pragma unroll
            for (int i = 0; i < 4; i++)
#pragma unroll
                for (int j = 0; j < 4; j++)
                    acc[i][j] = fmaf(wa[i], xa[j], acc[i][j]);
        }
        __syncthreads();
    }
    if (OUT_PM == 0) {
#pragma unroll
        for (int i = 0; i < 4; i++) {
            int m = m0 + ty * 4 + i;
            float bv = bias[m];
            float o0 = acc[i][0] + bv, o1 = acc[i][1] + bv;
            float o2 = acc[i][2] + bv, o3 = acc[i][3] + bv;
            *reinterpret_cast<float4*>(&out[((size_t)b * M + m) * NN + n0 + tx * 4]) =
                make_float4(o0, o1, o2, o3);
            if (offS >= 0) {
                // fused BN statistics: reduce this row's 64-wide n-tile across the
                // 16 tx lanes (lanes 0-15 / 16-31 of the warp form disjoint groups)
                float s = ((o0 + o1) + (o2 + o3));
                float q = ((o0 * o0 + o1 * o1) + (o2 * o2 + o3 * o3));
#pragma unroll
                for (int off = 1; off < 16; off <<= 1) {
                    s += __shfl_xor_sync(0xffffffffu, s, off);
                    q += __shfl_xor_sync(0xffffffffu, q, off);
                }
                if (tx == 0) {
                    atomicAdd(&g_stat[offS + m], s);
                    atomicAdd(&g_stat[offS + M + m], q);
                }
            }
        }
    } else {
#pragma unroll
        for (int j = 0; j < 4; j++) {
            int n = n0 + tx * 4 + j;
            int m = m0 + ty * 4;
            float4 o = make_float4(acc[0][j] + bias[m],     acc[1][j] + bias[m + 1],
                                   acc[2][j] + bias[m + 2], acc[3][j] + bias[m + 3]);
            *reinterpret_cast<float4*>(&out[((size_t)b * NN + n) * M + m]) = o;
        }
    }
}

// ---------------- weighted stats for BNg (counts * fc output) ----------------
__global__ void k_statw() {
    int b = blockIdx.y, mc = blockIdx.x;
    int r = threadIdx.x;
    float s = 0.f, q = 0.f;
    for (int m = mc * 128; m < mc * 128 + 128; m++) {
        float c = (float)g_cnt[b * NN + m];
        float v = g_y[((size_t)b * NN + m) * RR + r];
        s += c * v; q += c * v * v;
    }
    atomicAdd(&g_stat[256 + r], s);
    atomicAdd(&g_stat[384 + r], q);
}

// ---------------- finalize BN affine ----------------
__global__ void k_fin(const float* __restrict__ gamma, const float* __restrict__ beta,
                      int M, int offS, int offQ, float invcnt) {
    int m = blockIdx.x * 256 + threadIdx.x;
    if (m >= M) return;
    float mu = g_stat[offS + m] * invcnt;
    float var = g_stat[offQ + m] * invcnt - mu * mu;
    float sc = gamma[m] * rsqrtf(var + 1e-5f);
    g_aff[offS + m] = sc;
    g_aff[offQ + m] = beta[m] - mu * sc;
}

// ---------------- group max: x2[b][r][n2] = max_kg relu(bng(y[.,J])) ----------------
__global__ void k_gmax() {
    int n2 = blockIdx.x, b = blockIdx.y;
    __shared__ int sj[8];
    int r = threadIdx.x;
    if (r < 8)
        sj[r] = g_idx[((size_t)b * NN + r * 256 + (n2 >> 3)) * KK + (n2 & 7)];
    __syncthreads();
    float sc = g_aff[256 + r], sh = g_aff[384 + r];
    float u = 0.f;
#pragma unroll
    for (int kg = 0; kg < 8; kg++) {
        float v = g_y[((size_t)b * NN + sj[kg]) * RR + r];
        u = fmaxf(u, fmaxf(fmaf(v, sc, sh), 0.f));
    }
    g_x2c[((size_t)b * RR + r) * NN + n2] = u;
}

// ---------------- laplacian with faithful .view index algebra ----------------
__global__ void k_lap() {
    int n2 = blockIdx.x, b = blockIdx.y;
    int p = n2 >> 4, s = n2 & 15;
    __shared__ float xr[NN];
    __shared__ int si[2048];
    const float* src = g_x2c + ((size_t)b * RR + p) * NN;
    const int* ib = g_idx + ((size_t)b * NN + s * 128) * KK;
    for (int i = threadIdx.x; i < NN; i += 128) { xr[i] = src[i]; si[i] = ib[i]; }
    __syncthreads();
    int r2 = threadIdx.x;
    int u = r2 >> 4, j = r2 & 15;
    float acc = 0.f;
#pragma unroll
    for (int k2 = 0; k2 < 16; k2++)
        acc += xr[si[(k2 * 8 + u) * 16 + j]];
    float own = g_x2c[((size_t)b * RR + r2) * NN + n2];
    g_lapc[((size_t)b * RR + r2) * NN + n2] = own - acc * (1.f / 16.f);
}

// ---------------- final BN3 apply (float4) ----------------
__global__ void k_apply(float* __restrict__ out) {
    int i4 = blockIdx.x * 256 + threadIdx.x;      // float4 index
    int c = (i4 >> 9) & 511;                      // 512 float4 per channel row
    float sc = g_aff[1280 + c], sh = g_aff[1792 + c];
    float4 v = reinterpret_cast<const float4*>(g_y3)[i4];
    float4 o;
    o.x = fmaxf(fmaf(v.x, sc, sh), 0.f);
    o.y = fmaxf(fmaf(v.y, sc, sh), 0.f);
    o.z = fmaxf(fmaf(v.z, sc, sh), 0.f);
    o.w = fmaxf(fmaf(v.w, sc, sh), 0.f);
    reinterpret_cast<float4*>(out)[i4] = o;
}

extern "C" void kernel_launch(void* const* d_in, const int* in_sizes, int n_in,
                              void* d_out, int out_size) {
    const float* xyz   = (const float*)d_in[0];
    const float* feat  = (const float*)d_in[1];
    const float* w1    = (const float*)d_in[2];
    const float* b1    = (const float*)d_in[3];
    const float* bn1_g = (const float*)d_in[4];
    const float* bn1_b = (const float*)d_in[5];
    const float* fc_w  = (const float*)d_in[6];
    const float* fc_b  = (const float*)d_in[7];
    const float* bng_g = (const float*)d_in[8];
    const float* bng_b = (const float*)d_in[9];
    const float* lu_w  = (const float*)d_in[10];
    const float* lu_b  = (const float*)d_in[11];
    const float* bnl_g = (const float*)d_in[12];
    const float* bnl_b = (const float*)d_in[13];
    const float* w2    = (const float*)d_in[14];
    const float* b2    = (const float*)d_in[15];
    const float* bn2_g = (const float*)d_in[16];
    const float* bn2_b = (const float*)d_in[17];
    const float* w3    = (const float*)d_in[18];
    const float* b3    = (const float*)d_in[19];
    const float* bn3_g = (const float*)d_in[20];
    const float* bn3_b = (const float*)d_in[21];
    float* out = (float*)d_out;

    float *xpre, *y, *x2c, *lapc, *t, *y2, *y3, *aff;
    cudaGetSymbolAddress((void**)&xpre, g_xpre);
    cudaGetSymbolAddress((void**)&y,    g_y);
    cudaGetSymbolAddress((void**)&x2c,  g_x2c);
    cudaGetSymbolAddress((void**)&lapc, g_lapc);
    cudaGetSymbolAddress((void**)&t,    g_t);
    cudaGetSymbolAddress((void**)&y2,   g_y2);
    cudaGetSymbolAddress((void**)&y3,   g_y3);
    cudaGetSymbolAddress((void**)&aff,  g_aff);

    k_zero<<<128, 256>>>();
    k_knn<<<dim3(8, BB), 256>>>(xyz);
    k_cnt<<<BB, 512>>>();

    // mlp1: xpre = w1 @ feat + b1   (stats fused -> bn1 slots 0/128)
    k_gemm<0, 0><<<dim3(32, 2, BB), 256>>>(w1, feat, b1, nullptr, nullptr, nullptr, xpre, RR, CC, 0);
    k_fin<<<1, 256>>>(bn1_g, bn1_b, RR, 0, 128, 1.f / (BB * NN));

    // fc applied pre-gather: y[b][n][r] = fc_w @ relu(bn1(xpre)) + fc_b (point-major)
    k_gemm<1, 1><<<dim3(32, 2, BB), 256>>>(fc_w, xpre, fc_b, aff, aff + 128, nullptr, y, RR, RR, -1);
    k_statw<<<dim3(16, BB), 128>>>();
    k_fin<<<1, 256>>>(bng_g, bng_b, RR, 256, 384, 1.f / 262144.f);

    k_gmax<<<dim3(NN, BB), 128>>>();
    k_lap<<<dim3(NN, BB), 128>>>();

    // lu: t = lu_w @ lap + lu_b   (stats fused -> bnl slots 512/640)
    k_gemm<0, 0><<<dim3(32, 2, BB), 256>>>(lu_w, lapc, lu_b, nullptr, nullptr, nullptr, t, RR, RR, 512);
    k_fin<<<1, 256>>>(bnl_g, bnl_b, RR, 512, 640, 1.f / (BB * NN));

    // mlp2: y2 = w2 @ (x2 + relu(bnl(t))) + b2   (stats fused -> bn2 slots 768/1024)
    k_gemm<2, 0><<<dim3(32, 4, BB), 256>>>(w2, t, b2, aff + 512, aff + 640, x2c, y2, CC, RR, 768);
    k_fin<<<1, 256>>>(bn2_g, bn2_b, CC, 768, 1024, 1.f / (BB * NN));

    // mlp3: y3 = w3 @ (relu(bn2(y2)) + feat) + b3   (stats fused -> bn3 slots 1280/1792)
    k_gemm<2, 0><<<dim3(32, 8, BB), 256>>>(w3, y2, b3, aff + 768, aff + 1024, feat, y3, 2 * CC, CC, 1280);
    k_fin<<<2, 256>>>(bn3_g, bn3_b, 2 * CC, 1280, 1792, 1.f / (BB * NN));

    k_apply<<<16384, 256>>>(out);
}